// round 1
// baseline (speedup 1.0000x reference)
#include <cuda_runtime.h>
#include <math.h>

// Problem constants (bench shape: N=1024, IND=OUTD=32, E=8192)
#define NN 1024
#define DIM 32
#define MAXE 32768

// CSR scratch (device globals: no allocation allowed)
__device__ int g_offsets[NN + 1];
__device__ int g_colidx[MAXE];

// ---------------------------------------------------------------------------
// Build destination-keyed CSR in a single CTA (E=8192 is tiny).
// counts -> inclusive scan (Hillis-Steele) -> atomic fill.
// ---------------------------------------------------------------------------
__global__ void build_csr_kernel(const int* __restrict__ erow,
                                 const int* __restrict__ ecol, int E) {
    __shared__ int scnt[NN];
    __shared__ int sscan[NN];
    __shared__ int scur[NN];
    const int t = threadIdx.x;

    scnt[t] = 0;
    __syncthreads();
    for (int e = t; e < E; e += NN) atomicAdd(&scnt[erow[e]], 1);
    __syncthreads();

    const int v = scnt[t];
    sscan[t] = v;
    __syncthreads();
    #pragma unroll
    for (int d = 1; d < NN; d <<= 1) {
        int x = sscan[t];
        int y = (t >= d) ? sscan[t - d] : 0;
        __syncthreads();
        sscan[t] = x + y;
        __syncthreads();
    }
    const int incl = sscan[t];
    g_offsets[t + 1] = incl;
    if (t == 0) g_offsets[0] = 0;
    scur[t] = incl - v;   // exclusive offset -> fill cursor
    __syncthreads();

    for (int e = t; e < E; e += NN) {
        int r = erow[e];
        int p = atomicAdd(&scur[r], 1);
        g_colidx[p] = ecol[e];
    }
}

// ---------------------------------------------------------------------------
// Fused NGNN conv: one CTA per subgraph i.
//  smem: tX row buffer [1024][32] f32 (128KB) + mask row [1024] f32 (4KB)
//  Phase 1: tX[j] = (X[i,j]@W + b) * m[i,j]   (in-place in smem)
//  Phase 2: ret[i,j] = m[i,j] * sum_{e in CSR[j]} tX[col[e]]
// ---------------------------------------------------------------------------
__global__ void __launch_bounds__(512, 1)
ngnn_kernel(const float* __restrict__ X, const int* __restrict__ mask,
            const float* __restrict__ W, const float* __restrict__ b,
            float* __restrict__ out) {
    extern __shared__ float smem[];
    float* sX = smem;               // [NN * DIM]
    float* sm = smem + NN * DIM;    // [NN]

    const int tid  = threadIdx.x;
    const int lane = tid & 31;
    const int warp = tid >> 5;
    const int i    = blockIdx.x;

    // Per-lane: W column `lane` in registers, bias
    float wreg[DIM];
    #pragma unroll
    for (int d = 0; d < DIM; d++) wreg[d] = __ldg(&W[d * DIM + lane]);
    const float breg = __ldg(&b[lane]);

    // Stage X[i,:,:] into smem (coalesced float4) + mask row as float
    const float4* Xg  = (const float4*)(X + (size_t)i * NN * DIM);
    float4*       sXv = (float4*)sX;
    #pragma unroll
    for (int q = 0; q < (NN * DIM / 4) / 512; q++)
        sXv[tid + q * 512] = Xg[tid + q * 512];
    sm[tid]       = (float)mask[i * NN + tid];
    sm[tid + 512] = (float)mask[i * NN + tid + 512];
    __syncthreads();

    // Phase 1: MLP, warp-per-j, lane-per-output, in-place
    #pragma unroll 1
    for (int j = warp; j < NN; j += 16) {
        const float4* xr = (const float4*)(sX + j * DIM);
        float xv[DIM];
        #pragma unroll
        for (int q = 0; q < DIM / 4; q++) {
            float4 v = xr[q];                 // broadcast LDS.128
            xv[4 * q + 0] = v.x; xv[4 * q + 1] = v.y;
            xv[4 * q + 2] = v.z; xv[4 * q + 3] = v.w;
        }
        float acc = breg;
        #pragma unroll
        for (int d = 0; d < DIM; d++) acc = fmaf(xv[d], wreg[d], acc);
        sX[j * DIM + lane] = acc * sm[j];     // all lanes consumed x before this store
    }
    __syncthreads();

    // Phase 2: per-j aggregation over incoming edges from smem tX
    #pragma unroll 1
    for (int j = warp; j < NN; j += 16) {
        const int s = __ldg(&g_offsets[j]);
        const int e = __ldg(&g_offsets[j + 1]);
        float acc = 0.0f;
        #pragma unroll 2
        for (int p = s; p < e; p++) {
            int k = __ldg(&g_colidx[p]);
            acc += sX[k * DIM + lane];
        }
        out[((size_t)i * NN + j) * DIM + lane] = acc * sm[j];
    }
}

// ---------------------------------------------------------------------------
// Inputs (metadata order): X, mask, edge_row, edge_col, W, b ; output f32
// ---------------------------------------------------------------------------
extern "C" void kernel_launch(void* const* d_in, const int* in_sizes, int n_in,
                              void* d_out, int out_size) {
    const float* X    = (const float*)d_in[0];
    const int*   mask = (const int*)d_in[1];
    const int*   erow = (const int*)d_in[2];
    const int*   ecol = (const int*)d_in[3];
    const float* W    = (const float*)d_in[4];
    const float* b    = (const float*)d_in[5];
    float*       out  = (float*)d_out;
    const int E = in_sizes[2];

    const int smem_bytes = (NN * DIM + NN) * (int)sizeof(float);  // 132 KB
    cudaFuncSetAttribute(ngnn_kernel,
                         cudaFuncAttributeMaxDynamicSharedMemorySize, smem_bytes);

    build_csr_kernel<<<1, NN>>>(erow, ecol, E);
    ngnn_kernel<<<NN, 512, smem_bytes>>>(X, mask, W, b, out);
}

// round 2
// speedup vs baseline: 1.3311x; 1.3311x over previous
#include <cuda_runtime.h>

// Bench shape: N=1024, IND=OUTD=32, E=8192
#define NN    1024
#define DIM   32
#define EMAX  8192
#define CHUNK 256
#define NTHR  512
#define NWARP 16

// CSR scratch (device globals: allocation is forbidden)
__device__ int g_offsets[NN + 1];
__device__ int g_colidx[EMAX];   // stores col * DIM (pre-scaled element offset)

// ---------------------------------------------------------------------------
// Destination-keyed CSR in one CTA: counts -> scan -> atomic fill.
// ---------------------------------------------------------------------------
__global__ void build_csr_kernel(const int* __restrict__ erow,
                                 const int* __restrict__ ecol, int E) {
    __shared__ int scnt[NN];
    __shared__ int sscan[NN];
    __shared__ int scur[NN];
    const int t = threadIdx.x;

    scnt[t] = 0;
    __syncthreads();
    for (int e = t; e < E; e += NN) atomicAdd(&scnt[erow[e]], 1);
    __syncthreads();

    const int v = scnt[t];
    sscan[t] = v;
    __syncthreads();
    #pragma unroll
    for (int d = 1; d < NN; d <<= 1) {
        int x = sscan[t];
        int y = (t >= d) ? sscan[t - d] : 0;
        __syncthreads();
        sscan[t] = x + y;
        __syncthreads();
    }
    const int incl = sscan[t];
    g_offsets[t + 1] = incl;
    if (t == 0) g_offsets[0] = 0;
    scur[t] = incl - v;
    __syncthreads();

    for (int e = t; e < E; e += NN) {
        int r = erow[e];
        int p = atomicAdd(&scur[r], 1);
        g_colidx[p] = ecol[e] * DIM;
    }
}

// ---------------------------------------------------------------------------
// Fused NGNN conv, aggregation-first formulation:
//   ret[i,j] = m[i,j] * ( (sum_e m[i,col] X[i,col]) @ W + b * (sum_e m[i,col]) )
// One CTA per subgraph i. Masked-out j (≈50%) skip all work (warp-uniform).
// smem: masked X [1024][32] + Y chunk [256][32] + mask + cnt + CSR copy.
// ---------------------------------------------------------------------------
__global__ void __launch_bounds__(NTHR, 1)
ngnn_kernel(const float* __restrict__ X, const int* __restrict__ mask,
            const float* __restrict__ W, const float* __restrict__ b,
            float* __restrict__ out, int E) {
    extern __shared__ float smem[];
    float* sX  = smem;                      // 32768 f  (128 KB) masked X
    float* sY  = sX + NN * DIM;             //  8192 f  ( 32 KB) Y chunk
    float* smk = sY + CHUNK * DIM;          //  1024 f  (  4 KB) mask row
    float* sc  = smk + NN;                  //   256 f  (  1 KB) edge-mask counts
    int*   soff = (int*)(sc + CHUNK);       //  1032 i  (~ 4 KB, padded for align)
    int*   sidx = soff + 1032;              //  8192 i  ( 32 KB) colidx*DIM

    const int tid  = threadIdx.x;
    const int lane = tid & 31;
    const int warp = tid >> 5;
    const int i    = blockIdx.x;

    // W column `lane` + bias in registers
    float wreg[DIM];
    #pragma unroll
    for (int d = 0; d < DIM; d++) wreg[d] = __ldg(&W[d * DIM + lane]);
    const float breg = __ldg(&b[lane]);

    // Stage mask + CSR into smem
    smk[tid]       = (float)mask[i * NN + tid];
    smk[tid + 512] = (float)mask[i * NN + tid + 512];
    for (int t = tid; t <= NN; t += NTHR) soff[t] = g_offsets[t];
    {
        const int4* gci = (const int4*)g_colidx;
        int4* sci = (int4*)sidx;
        int nq = E >> 2;
        for (int q = tid; q < nq; q += NTHR) sci[q] = gci[q];
        for (int p = (nq << 2) + tid; p < E; p += NTHR) sidx[p] = g_colidx[p];
    }
    __syncthreads();

    // Stage X[i] masked: sX[k,:] = X[i,k,:] * m[i,k]   (coalesced float4)
    {
        const float4* Xg  = (const float4*)(X + (size_t)i * NN * DIM);
        float4* sXv = (float4*)sX;
        #pragma unroll
        for (int q = 0; q < (NN * DIM / 4) / NTHR; q++) {
            int f = tid + q * NTHR;
            float4 v = Xg[f];
            float m = smk[f >> 3];           // 8 float4 per 32-float row
            v.x *= m; v.y *= m; v.z *= m; v.w *= m;
            sXv[f] = v;
        }
    }
    __syncthreads();

    // Process j in chunks of 256 (Y buffer reuse)
    for (int cb = 0; cb < NN; cb += CHUNK) {
        // ---- Pass A: aggregate Y[j] = sum_e sX[col], cnt[j] = sum_e m[col]
        #pragma unroll 1
        for (int jo = warp; jo < CHUNK; jo += NWARP) {
            const int j = cb + jo;
            if (smk[j] == 0.0f) continue;      // warp-uniform skip
            const int s = soff[j];
            const int e = soff[j + 1];
            float acc = 0.0f, cnt = 0.0f;
            int p = s;
            for (; p + 4 <= e; p += 4) {       // 4 independent gathers in flight
                int k0 = sidx[p], k1 = sidx[p+1], k2 = sidx[p+2], k3 = sidx[p+3];
                float a0 = sX[k0 + lane], a1 = sX[k1 + lane];
                float a2 = sX[k2 + lane], a3 = sX[k3 + lane];
                float c0 = smk[k0 >> 5], c1 = smk[k1 >> 5];
                float c2 = smk[k2 >> 5], c3 = smk[k3 >> 5];
                acc += (a0 + a1) + (a2 + a3);
                cnt += (c0 + c1) + (c2 + c3);
            }
            for (; p < e; p++) {
                int k = sidx[p];
                acc += sX[k + lane];
                cnt += smk[k >> 5];
            }
            sY[jo * DIM + lane] = acc;
            if (lane == 0) sc[jo] = cnt;
        }
        __syncthreads();

        // ---- Pass B: MLP on Y (active j only), store; zeros for masked j
        #pragma unroll 1
        for (int jo = warp; jo < CHUNK; jo += NWARP) {
            const int j = cb + jo;
            float* o = out + ((size_t)i * NN + j) * DIM + lane;
            if (smk[j] == 0.0f) { *o = 0.0f; continue; }   // warp-uniform
            const float4* yr = (const float4*)(sY + jo * DIM);
            const float cnt = sc[jo];
            // 4 independent FMA chains (break the serial dependency)
            float acc0 = cnt * breg, acc1 = 0.0f, acc2 = 0.0f, acc3 = 0.0f;
            #pragma unroll
            for (int q = 0; q < DIM / 4; q++) {
                float4 v = yr[q];              // broadcast LDS.128
                acc0 = fmaf(v.x, wreg[4*q + 0], acc0);
                acc1 = fmaf(v.y, wreg[4*q + 1], acc1);
                acc2 = fmaf(v.z, wreg[4*q + 2], acc2);
                acc3 = fmaf(v.w, wreg[4*q + 3], acc3);
            }
            *o = (acc0 + acc1) + (acc2 + acc3);
        }
        __syncthreads();   // sY reused by next chunk
    }
}

// ---------------------------------------------------------------------------
// Inputs: X, mask, edge_row, edge_col, W, b ; output f32
// ---------------------------------------------------------------------------
extern "C" void kernel_launch(void* const* d_in, const int* in_sizes, int n_in,
                              void* d_out, int out_size) {
    const float* X    = (const float*)d_in[0];
    const int*   mask = (const int*)d_in[1];
    const int*   erow = (const int*)d_in[2];
    const int*   ecol = (const int*)d_in[3];
    const float* W    = (const float*)d_in[4];
    const float* b    = (const float*)d_in[5];
    float*       out  = (float*)d_out;
    const int E = in_sizes[2];

    // smem: (32768 + 8192 + 1024 + 256) floats + (1032 + 8192) ints
    const int smem_bytes = (32768 + 8192 + 1024 + 256) * 4 + (1032 + 8192) * 4;
    cudaFuncSetAttribute(ngnn_kernel,
                         cudaFuncAttributeMaxDynamicSharedMemorySize, smem_bytes);

    build_csr_kernel<<<1, NN>>>(erow, ecol, E);
    ngnn_kernel<<<NN, NTHR, smem_bytes>>>(X, mask, W, b, out, E);
}

// round 3
// speedup vs baseline: 1.6201x; 1.2171x over previous
#include <cuda_runtime.h>

// Bench shape: N=1024, IND=OUTD=32, E=8192
#define NN    1024
#define DIM   32
#define EMAX  8192
#define CHUNK 256
#define NTHR  1024
#define NWARP 32

// CSR scratch (device globals: allocation is forbidden)
__device__ int g_offsets[NN + 1];
__device__ int g_colidx[EMAX];   // stores col * DIM (pre-scaled element offset)

// ---------------------------------------------------------------------------
// Destination-keyed CSR in one CTA: counts -> scan -> atomic fill.
// ---------------------------------------------------------------------------
__global__ void build_csr_kernel(const int* __restrict__ erow,
                                 const int* __restrict__ ecol, int E) {
    __shared__ int scnt[NN];
    __shared__ int sscan[NN];
    __shared__ int scur[NN];
    const int t = threadIdx.x;

    scnt[t] = 0;
    __syncthreads();
    for (int e = t; e < E; e += NN) atomicAdd(&scnt[erow[e]], 1);
    __syncthreads();

    const int v = scnt[t];
    sscan[t] = v;
    __syncthreads();
    #pragma unroll
    for (int d = 1; d < NN; d <<= 1) {
        int x = sscan[t];
        int y = (t >= d) ? sscan[t - d] : 0;
        __syncthreads();
        sscan[t] = x + y;
        __syncthreads();
    }
    const int incl = sscan[t];
    g_offsets[t + 1] = incl;
    if (t == 0) g_offsets[0] = 0;
    scur[t] = incl - v;
    __syncthreads();

    for (int e = t; e < E; e += NN) {
        int r = erow[e];
        int p = atomicAdd(&scur[r], 1);
        g_colidx[p] = ecol[e] * DIM;
    }
}

// ---------------------------------------------------------------------------
// Fused NGNN conv, aggregation-first:
//   ret[i,j] = m[i,j] * ( (sum_e m[col] X[i,col]) @ W + b * (sum_e m[col]) )
// One CTA per subgraph i, 1024 threads (32 warps, occ 50%).
// Masked j (~50%) skip all work; masked k rows skip the X load entirely.
// ---------------------------------------------------------------------------
__global__ void __launch_bounds__(NTHR, 1)
ngnn_kernel(const float* __restrict__ X, const int* __restrict__ mask,
            const float* __restrict__ W, const float* __restrict__ b,
            float* __restrict__ out, int E) {
    extern __shared__ float smem[];
    float* sX   = smem;                     // 32768 f (128 KB) masked X
    float* sY   = sX + NN * DIM;            //  8192 f ( 32 KB) Y chunk
    float* smk  = sY + CHUNK * DIM;         //  1024 f (  4 KB) mask row
    float* sc   = smk + NN;                 //  1024 f (  4 KB) cnt[j] = sum m[col]
    int*   soff = (int*)(sc + NN);          //  1032 i
    int*   sidx = soff + 1032;              //  8192 i ( 32 KB) colidx*DIM

    const int tid  = threadIdx.x;
    const int lane = tid & 31;
    const int warp = tid >> 5;
    const int i    = blockIdx.x;

    // W column `lane` + bias in registers
    float wreg[DIM];
    #pragma unroll
    for (int d = 0; d < DIM; d++) wreg[d] = __ldg(&W[d * DIM + lane]);
    const float breg = __ldg(&b[lane]);

    // Stage mask + CSR into smem
    smk[tid] = (float)mask[i * NN + tid];
    for (int t = tid; t <= NN; t += NTHR) soff[t] = g_offsets[t];
    {
        const int4* gci = (const int4*)g_colidx;
        int4* sci = (int4*)sidx;
        int nq = E >> 2;
        for (int q = tid; q < nq; q += NTHR) sci[q] = gci[q];
        for (int p = (nq << 2) + tid; p < E; p += NTHR) sidx[p] = g_colidx[p];
    }
    __syncthreads();

    // Stage X[i] masked; skip the global load entirely when m[k]==0
    {
        const float4* Xg  = (const float4*)(X + (size_t)i * NN * DIM);
        float4* sXv = (float4*)sX;
        #pragma unroll
        for (int q = 0; q < (NN * DIM / 4) / NTHR; q++) {
            int f = tid + q * NTHR;
            float4 v = make_float4(0.f, 0.f, 0.f, 0.f);
            if (smk[f >> 3] != 0.0f) v = Xg[f];    // predicated LDG
            sXv[f] = v;
        }
    }

    // cnt[j] = sum_e m[col]  (thread-per-j, cheap; overlaps X staging latency)
    {
        int j = tid;
        const int s = soff[j], e = soff[j + 1];
        float c = 0.0f;
        for (int p = s; p < e; p++) c += smk[sidx[p] >> 5];
        sc[j] = c;
    }
    __syncthreads();

    // Process j in chunks of CHUNK (sY reuse)
    for (int cb = 0; cb < NN; cb += CHUNK) {
        // ---- Pass A: Y[j] = sum_e sX[col]   (warp-per-j, lane-per-dim)
        #pragma unroll 1
        for (int jo = warp; jo < CHUNK; jo += NWARP) {
            const int j = cb + jo;
            if (smk[j] == 0.0f) continue;          // warp-uniform skip
            const int s = soff[j];
            const int e = soff[j + 1];
            float acc = 0.0f;
            int p = s;
            for (; p + 4 <= e; p += 4) {           // 4 independent gathers
                int k0 = sidx[p],   k1 = sidx[p+1];
                int k2 = sidx[p+2], k3 = sidx[p+3];
                float a0 = sX[k0 + lane], a1 = sX[k1 + lane];
                float a2 = sX[k2 + lane], a3 = sX[k3 + lane];
                acc += (a0 + a1) + (a2 + a3);
            }
            for (; p < e; p++) acc += sX[sidx[p] + lane];
            sY[jo * DIM + lane] = acc;
        }
        __syncthreads();

        // ---- Pass B: MLP on Y, store; zeros for masked j
        #pragma unroll 1
        for (int jo = warp; jo < CHUNK; jo += NWARP) {
            const int j = cb + jo;
            float* o = out + ((size_t)i * NN + j) * DIM + lane;
            if (smk[j] == 0.0f) { *o = 0.0f; continue; }
            const float4* yr = (const float4*)(sY + jo * DIM);
            float acc0 = sc[j] * breg, acc1 = 0.f, acc2 = 0.f, acc3 = 0.f;
            #pragma unroll
            for (int q = 0; q < DIM / 4; q++) {
                float4 v = yr[q];                  // broadcast LDS.128
                acc0 = fmaf(v.x, wreg[4*q + 0], acc0);
                acc1 = fmaf(v.y, wreg[4*q + 1], acc1);
                acc2 = fmaf(v.z, wreg[4*q + 2], acc2);
                acc3 = fmaf(v.w, wreg[4*q + 3], acc3);
            }
            *o = (acc0 + acc1) + (acc2 + acc3);
        }
        __syncthreads();   // sY reused next chunk
    }
}

// ---------------------------------------------------------------------------
// Inputs: X, mask, edge_row, edge_col, W, b ; output f32
// ---------------------------------------------------------------------------
extern "C" void kernel_launch(void* const* d_in, const int* in_sizes, int n_in,
                              void* d_out, int out_size) {
    const float* X    = (const float*)d_in[0];
    const int*   mask = (const int*)d_in[1];
    const int*   erow = (const int*)d_in[2];
    const int*   ecol = (const int*)d_in[3];
    const float* W    = (const float*)d_in[4];
    const float* b    = (const float*)d_in[5];
    float*       out  = (float*)d_out;
    const int E = in_sizes[2];

    const int smem_bytes = (32768 + 8192 + 1024 + 1024) * 4 + (1032 + 8192) * 4;
    cudaFuncSetAttribute(ngnn_kernel,
                         cudaFuncAttributeMaxDynamicSharedMemorySize, smem_bytes);

    build_csr_kernel<<<1, NN>>>(erow, ecol, E);
    ngnn_kernel<<<NN, NTHR, smem_bytes>>>(X, mask, W, b, out, E);
}